// round 7
// baseline (speedup 1.0000x reference)
#include <cuda_runtime.h>

#define HWSZ 9216
#define IMG  96

// ---------------- device scratch (allocation-free) ----------------
__device__ float g_z   [2 * HWSZ * 512];
__device__ float g_z2  [2 * HWSZ * 512];
__device__ float g_qk  [2 * HWSZ * 128];
__device__ float g_v   [2 * HWSZ * 512];
__device__ float g_attn[2 * HWSZ * 192];
__device__ float g_acc [2 * HWSZ * 512];
__device__ float g_conv[2 * 512 * HWSZ];
__device__ float g_wqk [128 * 512];
__device__ float g_bqk [128];
__device__ float g_w9  [9 * 512 * 512];
__device__ float g_stat[128];

// ---------------- weight repacks ----------------
__global__ void pack_qk(const float* __restrict__ qw, const float* __restrict__ qb,
                        const float* __restrict__ kw, const float* __restrict__ kb,
                        float* __restrict__ wqk, float* __restrict__ bqk) {
    int i = blockIdx.x * 256 + threadIdx.x;
    if (i < 65536) {
        int m = i >> 9, k = i & 511;
        wqk[i] = (m < 64) ? qw[m * 512 + k] : kw[(m - 64) * 512 + k];
    }
    if (i < 128) bqk[i] = (i < 64) ? qb[i] : kb[i - 64];
}
__global__ void pack_w9(const float* __restrict__ w, float* __restrict__ w9) {
    int d = blockIdx.x * 256 + threadIdx.x;
    if (d < 9 * 512 * 512) {
        int s = d / (512 * 512), r = d % (512 * 512);
        int o = r >> 9, ic = r & 511;
        w9[d] = w[(o * 512 + ic) * 9 + s];
    }
}

// ---------------- fp32 GEMM: C[b][n][m] = An . Am^T + bias ----------------
// TRANSN=1: An is [b][K][N] (NCHW input).  TRANSN=0: An is [b][N][K].
template <bool TRANSN>
__global__ __launch_bounds__(256, 2)
void gemm128(const float* __restrict__ An, const float* __restrict__ Am,
             const float* __restrict__ bias, float* __restrict__ C,
             int M, int N, int K) {
    __shared__ float Xs[16][128];
    __shared__ float Ws[16][128];
    const int tid = threadIdx.x;
    const int n0 = blockIdx.x * 128, m0 = blockIdx.y * 128;
    const float* Anb = An + (size_t)blockIdx.z * K * N;
    float* Cb = C + (size_t)blockIdx.z * N * M;
    const int lm = tid & 127, lq = tid >> 7;
    const int lk = tid >> 5, ln = (tid & 31) << 2;

    float xr[8], wr[8], acc[8][8];
#pragma unroll
    for (int i = 0; i < 8; i++)
#pragma unroll
        for (int j = 0; j < 8; j++) acc[i][j] = 0.f;

    auto ldg = [&](int kt) {
        const int k0 = kt * 16;
#pragma unroll
        for (int p = 0; p < 2; p++) {
            const int q = lq + 2 * p;
            float4 v;
            if (TRANSN) v = *(const float4*)&Anb[(size_t)(k0 + lk + 8 * p) * N + n0 + ln];
            else        v = *(const float4*)&Anb[(size_t)(n0 + lm) * K + k0 + q * 4];
            xr[4*p]=v.x; xr[4*p+1]=v.y; xr[4*p+2]=v.z; xr[4*p+3]=v.w;
            float4 w = *(const float4*)&Am[(size_t)(m0 + lm) * K + k0 + q * 4];
            wr[4*p]=w.x; wr[4*p+1]=w.y; wr[4*p+2]=w.z; wr[4*p+3]=w.w;
        }
    };
    auto sts = [&]() {
#pragma unroll
        for (int p = 0; p < 2; p++) {
            const int q = lq + 2 * p;
            if (TRANSN) *(float4*)&Xs[lk + 8 * p][ln] = make_float4(xr[4*p], xr[4*p+1], xr[4*p+2], xr[4*p+3]);
            else {
#pragma unroll
                for (int j = 0; j < 4; j++) Xs[q * 4 + j][lm] = xr[4*p + j];
            }
#pragma unroll
            for (int j = 0; j < 4; j++) Ws[q * 4 + j][lm] = wr[4*p + j];
        }
    };

    const int T = K >> 4;
    const int tx = tid & 15, ty = tid >> 4;
    ldg(0);
    for (int kt = 0; kt < T; kt++) {
        sts();
        __syncthreads();
        if (kt + 1 < T) ldg(kt + 1);
#pragma unroll
        for (int k = 0; k < 16; k++) {
            float4 t0 = *(const float4*)&Xs[k][ty * 8];
            float4 t1 = *(const float4*)&Xs[k][ty * 8 + 4];
            float4 u0 = *(const float4*)&Ws[k][tx * 8];
            float4 u1 = *(const float4*)&Ws[k][tx * 8 + 4];
            float av[8] = {t0.x,t0.y,t0.z,t0.w,t1.x,t1.y,t1.z,t1.w};
            float bv[8] = {u0.x,u0.y,u0.z,u0.w,u1.x,u1.y,u1.z,u1.w};
#pragma unroll
            for (int i = 0; i < 8; i++)
#pragma unroll
                for (int j = 0; j < 8; j++) acc[i][j] += av[i] * bv[j];
        }
        __syncthreads();
    }
    float bb[8];
#pragma unroll
    for (int j = 0; j < 8; j++) bb[j] = bias ? bias[m0 + tx * 8 + j] : 0.f;
#pragma unroll
    for (int i = 0; i < 8; i++) {
        size_t row = (size_t)(n0 + ty * 8 + i) * M + m0 + tx * 8;
        *(float4*)&Cb[row]     = make_float4(acc[i][0]+bb[0], acc[i][1]+bb[1], acc[i][2]+bb[2], acc[i][3]+bb[3]);
        *(float4*)&Cb[row + 4] = make_float4(acc[i][4]+bb[4], acc[i][5]+bb[5], acc[i][6]+bb[6], acc[i][7]+bb[7]);
    }
}

// ---------------- conv3x3 = 9 accumulating shifted GEMMs (out NCHW) -------
__global__ __launch_bounds__(256, 2)
void conv3_kernel(const float* __restrict__ Z, const float* __restrict__ W9,
                  float* __restrict__ out) {
    __shared__ float Xs[16][128];
    __shared__ float Ws[16][128];
    __shared__ int srcn[9][128];
    const int tid = threadIdx.x;
    const int n0 = blockIdx.x * 128, m0 = blockIdx.y * 128, b = blockIdx.z;
    if (tid < 128) {
        int n = n0 + tid, y = n / IMG, x = n - y * IMG;
#pragma unroll
        for (int s = 0; s < 9; s++) {
            int sy = y + s / 3 - 1, sx = x + s % 3 - 1;
            srcn[s][tid] = (sy >= 0 && sy < IMG && sx >= 0 && sx < IMG) ? sy * IMG + sx : -1;
        }
    }
    __syncthreads();
    const float* Zb = Z + (size_t)b * HWSZ * 512;
    const int lm = tid & 127, lq = tid >> 7;
    float xr[8], wr[8], acc[8][8];
#pragma unroll
    for (int i = 0; i < 8; i++)
#pragma unroll
        for (int j = 0; j < 8; j++) acc[i][j] = 0.f;

    auto ldg = [&](int it) {
        const int s = it >> 5, k0 = (it & 31) << 4, sn = srcn[s][lm];
#pragma unroll
        for (int p = 0; p < 2; p++) {
            const int q = lq + 2 * p;
            float4 v = make_float4(0.f, 0.f, 0.f, 0.f);
            if (sn >= 0) v = *(const float4*)&Zb[(size_t)sn * 512 + k0 + q * 4];
            xr[4*p]=v.x; xr[4*p+1]=v.y; xr[4*p+2]=v.z; xr[4*p+3]=v.w;
            float4 w = *(const float4*)&W9[((size_t)s * 512 + m0 + lm) * 512 + k0 + q * 4];
            wr[4*p]=w.x; wr[4*p+1]=w.y; wr[4*p+2]=w.z; wr[4*p+3]=w.w;
        }
    };
    auto sts = [&]() {
#pragma unroll
        for (int p = 0; p < 2; p++) {
            const int q = lq + 2 * p;
#pragma unroll
            for (int j = 0; j < 4; j++) { Xs[q*4+j][lm] = xr[4*p+j]; Ws[q*4+j][lm] = wr[4*p+j]; }
        }
    };

    const int tx = tid & 15, ty = tid >> 4;
    ldg(0);
    for (int it = 0; it < 288; it++) {
        sts();
        __syncthreads();
        if (it + 1 < 288) ldg(it + 1);
#pragma unroll
        for (int k = 0; k < 16; k++) {
            float4 t0 = *(const float4*)&Xs[k][ty * 8];
            float4 t1 = *(const float4*)&Xs[k][ty * 8 + 4];
            float4 u0 = *(const float4*)&Ws[k][tx * 8];
            float4 u1 = *(const float4*)&Ws[k][tx * 8 + 4];
            float av[8] = {t0.x,t0.y,t0.z,t0.w,t1.x,t1.y,t1.z,t1.w};
            float bv[8] = {u0.x,u0.y,u0.z,u0.w,u1.x,u1.y,u1.z,u1.w};
#pragma unroll
            for (int i = 0; i < 8; i++)
#pragma unroll
                for (int j = 0; j < 8; j++) acc[i][j] += av[i] * bv[j];
        }
        __syncthreads();
    }
#pragma unroll
    for (int j = 0; j < 8; j++) {
        size_t chan = (size_t)b * 512 + m0 + tx * 8 + j;
#pragma unroll
        for (int i = 0; i < 8; i++)
            out[chan * HWSZ + n0 + ty * 8 + i] = acc[i][j];
    }
}

// ---------------- attention scores (dir 0 = e_h fixed w; dir 1 = e_w fixed h)
__global__ __launch_bounds__(256)
void scores_kernel(const float* __restrict__ qk, float* __restrict__ attn) {
    extern __shared__ float sm[];
    float* Qs = sm;            // [96][64]
    float* Ks = sm + 96 * 64;  // [96][68]
    const int fix = blockIdx.x, dir = blockIdx.y, b = blockIdx.z;
    const int tid = threadIdx.x;
    for (int idx = tid; idx < 96 * 32; idx += 256) {
        int p = idx >> 5, f = idx & 31;
        size_t row = (size_t)b * HWSZ + (dir == 0 ? p * IMG + fix : fix * IMG + p);
        float4 v = *(const float4*)&qk[row * 128 + f * 4];
        if (f < 16) *(float4*)&Qs[p * 64 + f * 4] = v;
        else        *(float4*)&Ks[p * 68 + (f - 16) * 4] = v;
    }
    __syncthreads();
    for (int idx = tid; idx < 9216; idx += 256) {
        int p = idx / 96, r = idx - p * 96;
        const float* qp = &Qs[p * 64];
        const float* kp = &Ks[r * 68];
        float a0 = 0.f, a1 = 0.f, a2 = 0.f, a3 = 0.f;
#pragma unroll
        for (int t = 0; t < 16; t++) {
            float4 a = *(const float4*)&qp[t * 4];
            float4 k = *(const float4*)&kp[t * 4];
            a0 += a.x * k.x; a1 += a.y * k.y; a2 += a.z * k.z; a3 += a.w * k.w;
        }
        float val = (a0 + a1) + (a2 + a3);
        if (dir == 0 && r == p) val = -1e30f;
        size_t o = (dir == 0)
            ? ((size_t)b * HWSZ + p * IMG + fix) * 192 + r
            : ((size_t)b * HWSZ + fix * IMG + p) * 192 + 96 + r;
        attn[o] = val;
    }
}

// ---------------- joint softmax over 192 logits; one warp / pixel ----------
__global__ __launch_bounds__(256)
void softmax_kernel(float* __restrict__ attn) {
    const int warp = threadIdx.x >> 5, lane = threadIdx.x & 31;
    const int pix = blockIdx.x * 8 + warp;
    float* p = attn + (size_t)pix * 192;
    float v[6];
#pragma unroll
    for (int t = 0; t < 6; t++) v[t] = p[lane + 32 * t];
    float m = v[0];
#pragma unroll
    for (int t = 1; t < 6; t++) m = fmaxf(m, v[t]);
#pragma unroll
    for (int off = 16; off > 0; off >>= 1) m = fmaxf(m, __shfl_xor_sync(0xffffffffu, m, off));
    float s = 0.f;
#pragma unroll
    for (int t = 0; t < 6; t++) { v[t] = __expf(v[t] - m); s += v[t]; }
#pragma unroll
    for (int off = 16; off > 0; off >>= 1) s += __shfl_xor_sync(0xffffffffu, s, off);
    float inv = 1.f / s;
#pragma unroll
    for (int t = 0; t < 6; t++) p[lane + 32 * t] = v[t] * inv;
}

// ---------------- aggregation along h ----------------
__global__ __launch_bounds__(256)
void agg_h_kernel(const float* __restrict__ V, const float* __restrict__ attn,
                  float* __restrict__ accb) {
    extern __shared__ float sm[];
    float* Vs = sm;             // [96][128]
    float* At = sm + 96 * 128;  // [i][h] stride 100
    const int w = blockIdx.x, c0 = blockIdx.y * 128, b = blockIdx.z;
    const int tid = threadIdx.x;
    for (int idx = tid; idx < 96 * 128; idx += 256) {
        int i = idx >> 7, cc = idx & 127;
        Vs[idx] = V[((size_t)b * HWSZ + i * IMG + w) * 512 + c0 + cc];
    }
    for (int idx = tid; idx < 9216; idx += 256) {
        int h = idx / 96, i = idx - h * 96;
        At[i * 100 + h] = attn[((size_t)b * HWSZ + h * IMG + w) * 192 + i];
    }
    __syncthreads();
    const int cc = tid & 127, h0 = (tid >> 7) * 48;
    float acc[48];
#pragma unroll
    for (int r = 0; r < 48; r++) acc[r] = 0.f;
    for (int i = 0; i < 96; i++) {
        float vv = Vs[i * 128 + cc];
        const float* ar = &At[i * 100 + h0];
#pragma unroll
        for (int r = 0; r < 12; r++) {
            float4 a = *(const float4*)&ar[r * 4];
            acc[4*r] += vv*a.x; acc[4*r+1] += vv*a.y; acc[4*r+2] += vv*a.z; acc[4*r+3] += vv*a.w;
        }
    }
#pragma unroll
    for (int h = 0; h < 48; h++)
        accb[((size_t)b * HWSZ + (h0 + h) * IMG + w) * 512 + c0 + cc] = acc[h];
}

// ---------------- aggregation along w + epilogue -------------------------
__global__ __launch_bounds__(256)
void agg_w_kernel(const float* __restrict__ V, const float* __restrict__ attn,
                  const float* __restrict__ accb, const float* __restrict__ zin,
                  const float* __restrict__ gamma, float* __restrict__ zout) {
    extern __shared__ float sm[];
    float* Vs = sm;
    float* At = sm + 96 * 128;
    const int h = blockIdx.x, c0 = blockIdx.y * 128, b = blockIdx.z;
    const int tid = threadIdx.x;
    for (int idx = tid; idx < 96 * 128; idx += 256) {
        int j = idx >> 7, cc = idx & 127;
        Vs[idx] = V[((size_t)b * HWSZ + h * IMG + j) * 512 + c0 + cc];
    }
    for (int idx = tid; idx < 9216; idx += 256) {
        int w = idx / 96, j = idx - w * 96;
        At[j * 100 + w] = attn[((size_t)b * HWSZ + h * IMG + w) * 192 + 96 + j];
    }
    __syncthreads();
    const int cc = tid & 127, w0 = (tid >> 7) * 48;
    float acc[48];
#pragma unroll
    for (int r = 0; r < 48; r++) acc[r] = 0.f;
    for (int j = 0; j < 96; j++) {
        float vv = Vs[j * 128 + cc];
        const float* ar = &At[j * 100 + w0];
#pragma unroll
        for (int r = 0; r < 12; r++) {
            float4 a = *(const float4*)&ar[r * 4];
            acc[4*r] += vv*a.x; acc[4*r+1] += vv*a.y; acc[4*r+2] += vv*a.z; acc[4*r+3] += vv*a.w;
        }
    }
    const float g = gamma[0];
#pragma unroll
    for (int w = 0; w < 48; w++) {
        size_t o = ((size_t)b * HWSZ + h * IMG + w0 + w) * 512 + c0 + cc;
        zout[o] = g * (acc[w] + accb[o]) + zin[o];
    }
}

// ---------------- GroupNorm ----------------
__global__ __launch_bounds__(256)
void gn_stats_kernel(const float* __restrict__ x, float* __restrict__ stat) {
    const float* p = x + (size_t)blockIdx.x * 147456;
    float s = 0.f, ss = 0.f;
    for (int idx = threadIdx.x * 4; idx < 147456; idx += 1024) {
        float4 v = *(const float4*)&p[idx];
        s  += (v.x + v.y) + (v.z + v.w);
        ss += (v.x*v.x + v.y*v.y) + (v.z*v.z + v.w*v.w);
    }
    __shared__ float rs[8], rss[8];
    const int lane = threadIdx.x & 31, warp = threadIdx.x >> 5;
#pragma unroll
    for (int off = 16; off > 0; off >>= 1) {
        s  += __shfl_xor_sync(0xffffffffu, s, off);
        ss += __shfl_xor_sync(0xffffffffu, ss, off);
    }
    if (lane == 0) { rs[warp] = s; rss[warp] = ss; }
    __syncthreads();
    if (threadIdx.x == 0) {
        float S = 0.f, SS = 0.f;
#pragma unroll
        for (int i = 0; i < 8; i++) { S += rs[i]; SS += rss[i]; }
        float mean = S / 147456.f;
        float var = SS / 147456.f - mean * mean;
        stat[2 * blockIdx.x] = mean;
        stat[2 * blockIdx.x + 1] = rsqrtf(var + 1e-5f);
    }
}

__global__ __launch_bounds__(256)
void gn_norm_kernel(const float* __restrict__ x, const float* __restrict__ gam,
                    const float* __restrict__ bet, const float* __restrict__ stat,
                    float* __restrict__ out) {
    int i4 = blockIdx.x * 256 + threadIdx.x;
    int base = i4 * 4;
    int c = (base / HWSZ) & 511;
    int b = base / (512 * HWSZ);
    int sg = b * 32 + (c >> 4);
    float mean = stat[2 * sg], rstd = stat[2 * sg + 1];
    float sc = rstd * gam[c], sh = bet[c] - mean * sc;
    float4 v = *(const float4*)&x[base];
    *(float4*)&out[base] = make_float4(v.x*sc+sh, v.y*sc+sh, v.z*sc+sh, v.w*sc+sh);
}

// ---------------- launch ----------------
extern "C" void kernel_launch(void* const* d_in, const int* in_sizes, int n_in,
                              void* d_out, int out_size) {
    const float* x    = (const float*)d_in[0];
    const float* c1w  = (const float*)d_in[1];
    const float* c1b  = (const float*)d_in[2];
    const float* qw   = (const float*)d_in[3];
    const float* qb   = (const float*)d_in[4];
    const float* kw   = (const float*)d_in[5];
    const float* kb   = (const float*)d_in[6];
    const float* vw   = (const float*)d_in[7];
    const float* vb   = (const float*)d_in[8];
    const float* gam  = (const float*)d_in[9];
    const float* cow  = (const float*)d_in[10];
    const float* gng  = (const float*)d_in[11];
    const float* gnb  = (const float*)d_in[12];
    float* out = (float*)d_out;

    void *pz, *pz2, *pqk, *pv, *pattn, *pacc, *pconv, *pwqk, *pbqk, *pw9, *pstat;
    cudaGetSymbolAddress(&pz, g_z);     cudaGetSymbolAddress(&pz2, g_z2);
    cudaGetSymbolAddress(&pqk, g_qk);   cudaGetSymbolAddress(&pv, g_v);
    cudaGetSymbolAddress(&pattn, g_attn); cudaGetSymbolAddress(&pacc, g_acc);
    cudaGetSymbolAddress(&pconv, g_conv); cudaGetSymbolAddress(&pwqk, g_wqk);
    cudaGetSymbolAddress(&pbqk, g_bqk); cudaGetSymbolAddress(&pw9, g_w9);
    cudaGetSymbolAddress(&pstat, g_stat);
    float *z = (float*)pz, *z2 = (float*)pz2, *qk = (float*)pqk, *v = (float*)pv;
    float *attn = (float*)pattn, *acc = (float*)pacc, *cv = (float*)pconv;
    float *wqk = (float*)pwqk, *bqk = (float*)pbqk, *w9 = (float*)pw9, *st = (float*)pstat;

    const int SC_SM = 50688, AG_SM = 87552;
    cudaFuncSetAttribute(scores_kernel, cudaFuncAttributeMaxDynamicSharedMemorySize, SC_SM);
    cudaFuncSetAttribute(agg_h_kernel,  cudaFuncAttributeMaxDynamicSharedMemorySize, AG_SM);
    cudaFuncSetAttribute(agg_w_kernel,  cudaFuncAttributeMaxDynamicSharedMemorySize, AG_SM);

    pack_qk<<<256, 256>>>(qw, qb, kw, kb, wqk, bqk);
    pack_w9<<<9216, 256>>>(cow, w9);

    // conv1: x [2][2048][9216] -> z [2][9216][512]
    gemm128<true><<<dim3(72, 4, 2), 256>>>(x, c1w, c1b, z, 512, HWSZ, 2048);

    for (int it = 0; it < 2; it++) {
        float* zi = it ? z2 : z;
        float* zo = it ? z  : z2;
        gemm128<false><<<dim3(72, 1, 2), 256>>>(zi, wqk, bqk, qk, 128, HWSZ, 512);
        gemm128<false><<<dim3(72, 4, 2), 256>>>(zi, vw, vb, v, 512, HWSZ, 512);
        scores_kernel<<<dim3(96, 2, 2), 256, SC_SM>>>(qk, attn);
        softmax_kernel<<<2304, 256>>>(attn);
        agg_h_kernel<<<dim3(96, 4, 2), 256, AG_SM>>>(v, attn, acc);
        agg_w_kernel<<<dim3(96, 4, 2), 256, AG_SM>>>(v, attn, acc, zi, gam, zo);
    }

    conv3_kernel<<<dim3(72, 4, 2), 256>>>(z, w9, cv);
    gn_stats_kernel<<<64, 256>>>(cv, st);
    gn_norm_kernel<<<2 * 512 * HWSZ / 1024, 256>>>(cv, gng, gnb, st, out);
}

// round 9
// speedup vs baseline: 1.9795x; 1.9795x over previous
#include <cuda_runtime.h>
#include <cuda_bf16.h>
#include <cstdint>

#define HWSZ 9216
#define IMG  96
typedef __nv_bfloat16 bf16;

// ---------------- device scratch ----------------
__device__ bf16 g_xh[2 * HWSZ * 2048];
__device__ bf16 g_xl[2 * HWSZ * 2048];
__device__ bf16 g_zh[2 * HWSZ * 512];
__device__ bf16 g_zl[2 * HWSZ * 512];
__device__ float g_z   [2 * HWSZ * 512];
__device__ float g_z2  [2 * HWSZ * 512];
__device__ float g_qk  [2 * HWSZ * 128];
__device__ float g_v   [2 * HWSZ * 512];
__device__ float g_attn[2 * HWSZ * 192];
__device__ float g_acc [2 * HWSZ * 512];
__device__ float g_cl  [2 * HWSZ * 512];
__device__ bf16 g_c1h[512 * 2048], g_c1l[512 * 2048];
__device__ bf16 g_qkh[128 * 512],  g_qkl[128 * 512];
__device__ bf16 g_vh [512 * 512],  g_vl [512 * 512];
__device__ bf16 g_w9h[9 * 512 * 512], g_w9l[9 * 512 * 512];
__device__ float g_bqk[128];
__device__ float g_stat[128];

// ---------------- helpers ----------------
__device__ __forceinline__ uint32_t s2u(const void* p) {
    uint32_t a;
    asm("{ .reg .u64 t; cvta.to.shared.u64 t, %1; cvt.u32.u64 %0, t; }" : "=r"(a) : "l"(p));
    return a;
}
__device__ __forceinline__ void bsplit(float v, bf16* h, bf16* l) {
    bf16 hh = __float2bfloat16(v);
    *h = hh;
    *l = __float2bfloat16(v - __bfloat162float(hh));
}
__device__ __forceinline__ void mma16816(float* d, const uint32_t* a, const uint32_t* b) {
    asm volatile(
        "mma.sync.aligned.m16n8k16.row.col.f32.bf16.bf16.f32 "
        "{%0,%1,%2,%3}, {%4,%5,%6,%7}, {%8,%9}, {%0,%1,%2,%3};"
        : "+f"(d[0]), "+f"(d[1]), "+f"(d[2]), "+f"(d[3])
        : "r"(a[0]), "r"(a[1]), "r"(a[2]), "r"(a[3]), "r"(b[0]), "r"(b[1]));
}
__device__ __forceinline__ void cpasync16(uint32_t s, const void* g) {
    asm volatile("cp.async.cg.shared.global [%0], [%1], 16;" :: "r"(s), "l"(g));
}

// ---------------- packing / splitting ----------------
__global__ void split_x(const float* __restrict__ x, bf16* __restrict__ xh,
                        bf16* __restrict__ xl) {
    __shared__ float t[32][33];
    const int p0 = blockIdx.x * 32, c0 = blockIdx.y * 32, b = blockIdx.z;
    const int tx = threadIdx.x & 31, ty = threadIdx.x >> 5;
#pragma unroll
    for (int k = 0; k < 4; k++) {
        int cl = ty + k * 8;
        t[cl][tx] = x[((size_t)b * 2048 + c0 + cl) * HWSZ + p0 + tx];
    }
    __syncthreads();
#pragma unroll
    for (int k = 0; k < 4; k++) {
        int pl = ty + k * 8;
        float v = t[tx][pl];
        size_t o = ((size_t)b * HWSZ + p0 + pl) * 2048 + c0 + tx;
        bsplit(v, &xh[o], &xl[o]);
    }
}
__global__ void split_w(const float* __restrict__ w, bf16* __restrict__ wh,
                        bf16* __restrict__ wl, int n) {
    int i = blockIdx.x * 256 + threadIdx.x;
    if (i < n) bsplit(w[i], &wh[i], &wl[i]);
}
__global__ void split_qk(const float* __restrict__ qw, const float* __restrict__ kw,
                         bf16* __restrict__ wh, bf16* __restrict__ wl) {
    int i = blockIdx.x * 256 + threadIdx.x;
    if (i >= 65536) return;
    int m = i >> 9, k = i & 511;
    float v = (m < 64) ? qw[m * 512 + k] : kw[(m - 64) * 512 + k];
    bsplit(v, &wh[i], &wl[i]);
}
__global__ void pack_bias(const float* __restrict__ qb, const float* __restrict__ kb,
                          float* __restrict__ bqk) {
    int i = threadIdx.x;
    bqk[i] = (i < 64) ? qb[i] : kb[i - 64];
}
__global__ void split_w9(const float* __restrict__ w, bf16* __restrict__ wh,
                         bf16* __restrict__ wl) {
    int d = blockIdx.x * 256 + threadIdx.x;
    if (d >= 9 * 512 * 512) return;
    int s = d / (512 * 512), r = d % (512 * 512);
    int o = r >> 9, ic = r & 511;
    bsplit(w[(o * 512 + ic) * 9 + s], &wh[d], &wl[d]);
}

// ---------------- bf16-split tensor-core GEMM (mma.sync HMMA path) --------
// D[128 pix][128 ch] = A[pix][K] . B[ch][K]^T via Ah*Bh + Ah*Bl + Al*Bh
// MODE 0: conv1 (fp32 out + bf16 hi/lo out), 1: qk, 2: v, 3: conv3 (9 shifts)
// smem: srcn (9*128 ints) then 2 buffers x 4 operands x [128 rows][40 bf16]
#define OPSZ 5120            // elems per operand tile (128*40)
#define BUFSZ (4 * OPSZ)
#define MG_SMEM (4864 + 2 * BUFSZ * 2)
template <int MODE>
__global__ __launch_bounds__(256, 1)
void mma_gemm(const bf16* __restrict__ Ah, const bf16* __restrict__ Al,
              const bf16* __restrict__ Bh, const bf16* __restrict__ Bl,
              const float* __restrict__ bias, float* __restrict__ outf,
              bf16* __restrict__ oh, bf16* __restrict__ ol,
              int K, int Mtot)
{
    extern __shared__ char smem[];
    int* srcn = (int*)smem;
    bf16* tiles = (bf16*)(smem + 4864);
    const int tid = threadIdx.x, wid = tid >> 5, lane = tid & 31;
    const int n0 = blockIdx.x * 128, m0 = blockIdx.y * 128, b = blockIdx.z;

    if (MODE == 3 && tid < 128) {
        int n = n0 + tid, y = n / IMG, x = n - y * IMG;
#pragma unroll
        for (int s = 0; s < 9; s++) {
            int sy = y + s / 3 - 1, sx = x + s % 3 - 1;
            srcn[s * 128 + tid] = (sy >= 0 && sy < IMG && sx >= 0 && sx < IMG) ? sy * IMG + sx : -1;
        }
    }
    __syncthreads();

    const int g = tid >> 6, u = tid & 63, q = u & 3, rs = u >> 2;
    const bf16* srcp = (g == 0) ? Ah : (g == 1) ? Al : (g == 2) ? Bh : Bl;
    const int nch = (MODE == 3) ? 144 : (K >> 5);

    auto load_chunk = [&](int i) {
        bf16* t = tiles + (i & 1) * BUFSZ + g * OPSZ;
        int s = 0, k0;
        if (MODE == 3) { s = i >> 4; k0 = (i & 15) << 5; } else { k0 = i << 5; }
#pragma unroll
        for (int j = 0; j < 8; j++) {
            int row = rs + j * 16;
            uint32_t sa = s2u(t + row * 40 + q * 8);
            if (g < 2) {
                long rn = -1;
                if (MODE == 3) { int sn = srcn[s * 128 + row]; if (sn >= 0) rn = sn; }
                else rn = n0 + row;
                if (rn >= 0)
                    cpasync16(sa, srcp + ((size_t)b * HWSZ + rn) * (size_t)K + k0 + q * 8);
                else
                    *(uint4*)(t + row * 40 + q * 8) = make_uint4(0, 0, 0, 0);
            } else {
                size_t mrow = (MODE == 3) ? ((size_t)s * 512 + m0 + row) : (size_t)(m0 + row);
                cpasync16(sa, srcp + mrow * (size_t)K + k0 + q * 8);
            }
        }
        asm volatile("cp.async.commit_group;" ::: "memory");
    };

    float acc[4][4][4];
#pragma unroll
    for (int mi = 0; mi < 4; mi++)
#pragma unroll
        for (int ni = 0; ni < 4; ni++)
#pragma unroll
            for (int r = 0; r < 4; r++) acc[mi][ni][r] = 0.f;

    const int wm = wid >> 2, wn = wid & 3;
    const int lr = lane >> 2, lc = (lane & 3) * 2;

    load_chunk(0);
    asm volatile("cp.async.wait_group 0;" ::: "memory");
    __syncthreads();

    for (int i = 0; i < nch; i++) {
        if (i + 1 < nch) load_chunk(i + 1);
        const bf16* tb = tiles + (i & 1) * BUFSZ;
        const bf16* pAh = tb;
        const bf16* pAl = tb + OPSZ;
        const bf16* pBh = tb + 2 * OPSZ;
        const bf16* pBl = tb + 3 * OPSZ;
#pragma unroll
        for (int ks = 0; ks < 2; ks++) {
            const int kc = ks * 16 + lc;
            uint32_t ah[4][4], al[4][4], bh[4][2], bl[4][2];
#pragma unroll
            for (int mi = 0; mi < 4; mi++) {
                const int r0 = wm * 64 + mi * 16 + lr;
                ah[mi][0] = *(const uint32_t*)(pAh + r0 * 40 + kc);
                ah[mi][1] = *(const uint32_t*)(pAh + (r0 + 8) * 40 + kc);
                ah[mi][2] = *(const uint32_t*)(pAh + r0 * 40 + kc + 8);
                ah[mi][3] = *(const uint32_t*)(pAh + (r0 + 8) * 40 + kc + 8);
                al[mi][0] = *(const uint32_t*)(pAl + r0 * 40 + kc);
                al[mi][1] = *(const uint32_t*)(pAl + (r0 + 8) * 40 + kc);
                al[mi][2] = *(const uint32_t*)(pAl + r0 * 40 + kc + 8);
                al[mi][3] = *(const uint32_t*)(pAl + (r0 + 8) * 40 + kc + 8);
            }
#pragma unroll
            for (int ni = 0; ni < 4; ni++) {
                const int n = wn * 32 + ni * 8 + lr;
                bh[ni][0] = *(const uint32_t*)(pBh + n * 40 + kc);
                bh[ni][1] = *(const uint32_t*)(pBh + n * 40 + kc + 8);
                bl[ni][0] = *(const uint32_t*)(pBl + n * 40 + kc);
                bl[ni][1] = *(const uint32_t*)(pBl + n * 40 + kc + 8);
            }
#pragma unroll
            for (int mi = 0; mi < 4; mi++)
#pragma unroll
                for (int ni = 0; ni < 4; ni++) {
                    mma16816(acc[mi][ni], ah[mi], bh[ni]);
                    mma16816(acc[mi][ni], ah[mi], bl[ni]);
                    mma16816(acc[mi][ni], al[mi], bh[ni]);
                }
        }
        if (i + 1 < nch) asm volatile("cp.async.wait_group 0;" ::: "memory");
        __syncthreads();
    }

    // epilogue
#pragma unroll
    for (int mi = 0; mi < 4; mi++) {
#pragma unroll
        for (int ni = 0; ni < 4; ni++) {
            const int ch = m0 + wn * 32 + ni * 8 + lc;
            float b0 = 0.f, b1 = 0.f;
            if (MODE != 3) { b0 = __ldg(bias + ch); b1 = __ldg(bias + ch + 1); }
#pragma unroll
            for (int hh = 0; hh < 2; hh++) {
                const int pix = n0 + wm * 64 + mi * 16 + lr + hh * 8;
                const size_t prow = (size_t)b * HWSZ + pix;
                float v0 = acc[mi][ni][hh * 2] + b0;
                float v1 = acc[mi][ni][hh * 2 + 1] + b1;
                float2 vv; vv.x = v0; vv.y = v1;
                *(float2*)(outf + prow * (size_t)Mtot + ch) = vv;
                if (MODE == 0) {
                    size_t o = prow * 512 + ch;
                    __nv_bfloat162 th, tl;
                    bf16 h0, l0, h1, l1;
                    bsplit(v0, &h0, &l0);
                    bsplit(v1, &h1, &l1);
                    th.x = h0; th.y = h1; tl.x = l0; tl.y = l1;
                    *(__nv_bfloat162*)(oh + o) = th;
                    *(__nv_bfloat162*)(ol + o) = tl;
                }
            }
        }
    }
}

// ---------------- attention scores ----------------
__global__ __launch_bounds__(256)
void scores_kernel(const float* __restrict__ qk, float* __restrict__ attn) {
    extern __shared__ float sm[];
    float* Qs = sm;
    float* Ks = sm + 96 * 64;
    const int fix = blockIdx.x, dir = blockIdx.y, b = blockIdx.z;
    const int tid = threadIdx.x;
    for (int idx = tid; idx < 96 * 32; idx += 256) {
        int p = idx >> 5, f = idx & 31;
        size_t row = (size_t)b * HWSZ + (dir == 0 ? p * IMG + fix : fix * IMG + p);
        float4 v = *(const float4*)&qk[row * 128 + f * 4];
        if (f < 16) *(float4*)&Qs[p * 64 + f * 4] = v;
        else        *(float4*)&Ks[p * 68 + (f - 16) * 4] = v;
    }
    __syncthreads();
    for (int idx = tid; idx < 9216; idx += 256) {
        int p = idx / 96, r = idx - p * 96;
        const float* qp = &Qs[p * 64];
        const float* kp = &Ks[r * 68];
        float a0 = 0.f, a1 = 0.f, a2 = 0.f, a3 = 0.f;
#pragma unroll
        for (int t = 0; t < 16; t++) {
            float4 a = *(const float4*)&qp[t * 4];
            float4 k = *(const float4*)&kp[t * 4];
            a0 += a.x * k.x; a1 += a.y * k.y; a2 += a.z * k.z; a3 += a.w * k.w;
        }
        float val = (a0 + a1) + (a2 + a3);
        if (dir == 0 && r == p) val = -1e30f;
        size_t o = (dir == 0)
            ? ((size_t)b * HWSZ + p * IMG + fix) * 192 + r
            : ((size_t)b * HWSZ + fix * IMG + p) * 192 + 96 + r;
        attn[o] = val;
    }
}

__global__ __launch_bounds__(256)
void softmax_kernel(float* __restrict__ attn) {
    const int warp = threadIdx.x >> 5, lane = threadIdx.x & 31;
    const int pix = blockIdx.x * 8 + warp;
    float* p = attn + (size_t)pix * 192;
    float v[6];
#pragma unroll
    for (int t = 0; t < 6; t++) v[t] = p[lane + 32 * t];
    float m = v[0];
#pragma unroll
    for (int t = 1; t < 6; t++) m = fmaxf(m, v[t]);
#pragma unroll
    for (int off = 16; off > 0; off >>= 1) m = fmaxf(m, __shfl_xor_sync(0xffffffffu, m, off));
    float s = 0.f;
#pragma unroll
    for (int t = 0; t < 6; t++) { v[t] = __expf(v[t] - m); s += v[t]; }
#pragma unroll
    for (int off = 16; off > 0; off >>= 1) s += __shfl_xor_sync(0xffffffffu, s, off);
    float inv = 1.f / s;
#pragma unroll
    for (int t = 0; t < 6; t++) p[lane + 32 * t] = v[t] * inv;
}

// ---------------- aggregation along h ----------------
__global__ __launch_bounds__(256)
void agg_h_kernel(const float* __restrict__ V, const float* __restrict__ attn,
                  float* __restrict__ accb) {
    extern __shared__ float sm[];
    float* Vs = sm;
    float* At = sm + 96 * 128;
    const int w = blockIdx.x, c0 = blockIdx.y * 128, b = blockIdx.z;
    const int tid = threadIdx.x;
    for (int idx = tid; idx < 96 * 128; idx += 256) {
        int i = idx >> 7, cc = idx & 127;
        Vs[idx] = V[((size_t)b * HWSZ + i * IMG + w) * 512 + c0 + cc];
    }
    for (int idx = tid; idx < 9216; idx += 256) {
        int h = idx / 96, i = idx - h * 96;
        At[i * 100 + h] = attn[((size_t)b * HWSZ + h * IMG + w) * 192 + i];
    }
    __syncthreads();
    const int cc = tid & 127, h0 = (tid >> 7) * 48;
    float acc[48];
#pragma unroll
    for (int r = 0; r < 48; r++) acc[r] = 0.f;
    for (int i = 0; i < 96; i++) {
        float vv = Vs[i * 128 + cc];
        const float* ar = &At[i * 100 + h0];
#pragma unroll
        for (int r = 0; r < 12; r++) {
            float4 a = *(const float4*)&ar[r * 4];
            acc[4*r] += vv*a.x; acc[4*r+1] += vv*a.y; acc[4*r+2] += vv*a.z; acc[4*r+3] += vv*a.w;
        }
    }
#pragma unroll
    for (int h = 0; h < 48; h++)
        accb[((size_t)b * HWSZ + (h0 + h) * IMG + w) * 512 + c0 + cc] = acc[h];
}

// ---------------- aggregation along w + epilogue (emits bf16 hi/lo) ------
__global__ __launch_bounds__(256)
void agg_w_kernel(const float* __restrict__ V, const float* __restrict__ attn,
                  const float* __restrict__ accb, const float* __restrict__ zin,
                  const float* __restrict__ gamma, float* __restrict__ zout,
                  bf16* __restrict__ zh, bf16* __restrict__ zl) {
    extern __shared__ float sm[];
    float* Vs = sm;
    float* At = sm + 96 * 128;
    const int h = blockIdx.x, c0 = blockIdx.y * 128, b = blockIdx.z;
    const int tid = threadIdx.x;
    for (int idx = tid; idx < 96 * 128; idx += 256) {
        int j = idx >> 7, cc = idx & 127;
        Vs[idx] = V[((size_t)b * HWSZ + h * IMG + j) * 512 + c0 + cc];
    }
    for (int idx = tid; idx < 9216; idx += 256) {
        int w = idx / 96, j = idx - w * 96;
        At[j * 100 + w] = attn[((size_t)b * HWSZ + h * IMG + w) * 192 + 96 + j];
    }
    __syncthreads();
    const int cc = tid & 127, w0 = (tid >> 7) * 48;
    float acc[48];
#pragma unroll
    for (int r = 0; r < 48; r++) acc[r] = 0.f;
    for (int j = 0; j < 96; j++) {
        float vv = Vs[j * 128 + cc];
        const float* ar = &At[j * 100 + w0];
#pragma unroll
        for (int r = 0; r < 12; r++) {
            float4 a = *(const float4*)&ar[r * 4];
            acc[4*r] += vv*a.x; acc[4*r+1] += vv*a.y; acc[4*r+2] += vv*a.z; acc[4*r+3] += vv*a.w;
        }
    }
    const float g = gamma[0];
#pragma unroll
    for (int w = 0; w < 48; w++) {
        size_t o = ((size_t)b * HWSZ + h * IMG + w0 + w) * 512 + c0 + cc;
        float val = g * (acc[w] + accb[o]) + zin[o];
        zout[o] = val;
        bsplit(val, &zh[o], &zl[o]);
    }
}

// ---------------- GroupNorm ----------------
__global__ __launch_bounds__(256)
void gn_stats_cl(const float* __restrict__ x, float* __restrict__ stat) {
    const int b = blockIdx.x >> 5, gg = blockIdx.x & 31;
    const float* base = x + (size_t)b * HWSZ * 512 + gg * 16;
    float s = 0.f, ss = 0.f;
    for (int idx = threadIdx.x; idx < HWSZ * 4; idx += 256) {
        int pix = idx >> 2, q = idx & 3;
        float4 v = *(const float4*)(base + (size_t)pix * 512 + q * 4);
        s  += (v.x + v.y) + (v.z + v.w);
        ss += (v.x*v.x + v.y*v.y) + (v.z*v.z + v.w*v.w);
    }
    __shared__ float rs[8], rss[8];
    const int lane = threadIdx.x & 31, warp = threadIdx.x >> 5;
#pragma unroll
    for (int off = 16; off > 0; off >>= 1) {
        s  += __shfl_xor_sync(0xffffffffu, s, off);
        ss += __shfl_xor_sync(0xffffffffu, ss, off);
    }
    if (lane == 0) { rs[warp] = s; rss[warp] = ss; }
    __syncthreads();
    if (threadIdx.x == 0) {
        float S = 0.f, SS = 0.f;
#pragma unroll
        for (int i = 0; i < 8; i++) { S += rs[i]; SS += rss[i]; }
        float mean = S / 147456.f;
        float var = SS / 147456.f - mean * mean;
        stat[2 * blockIdx.x] = mean;
        stat[2 * blockIdx.x + 1] = rsqrtf(var + 1e-5f);
    }
}

__global__ __launch_bounds__(256)
void gn_out_kernel(const float* __restrict__ cl, const float* __restrict__ gam,
                   const float* __restrict__ bet, const float* __restrict__ stat,
                   float* __restrict__ out) {
    __shared__ float t[32][33];
    const int p0 = blockIdx.x * 32, c0 = blockIdx.y * 32, b = blockIdx.z;
    const int tx = threadIdx.x & 31, ty = threadIdx.x >> 5;
#pragma unroll
    for (int k = 0; k < 4; k++) {
        int pl = ty + k * 8;
        t[pl][tx] = cl[((size_t)b * HWSZ + p0 + pl) * 512 + c0 + tx];
    }
    __syncthreads();
#pragma unroll
    for (int k = 0; k < 4; k++) {
        int c = c0 + ty + k * 8;
        int sg = b * 32 + (c >> 4);
        float sc = stat[2 * sg + 1] * gam[c];
        float sh = bet[c] - stat[2 * sg] * sc;
        out[((size_t)b * 512 + c) * HWSZ + p0 + tx] = t[tx][ty + k * 8] * sc + sh;
    }
}

// ---------------- launch ----------------
extern "C" void kernel_launch(void* const* d_in, const int* in_sizes, int n_in,
                              void* d_out, int out_size) {
    const float* x   = (const float*)d_in[0];
    const float* c1w = (const float*)d_in[1];
    const float* c1b = (const float*)d_in[2];
    const float* qw  = (const float*)d_in[3];
    const float* qb  = (const float*)d_in[4];
    const float* kw  = (const float*)d_in[5];
    const float* kb  = (const float*)d_in[6];
    const float* vw  = (const float*)d_in[7];
    const float* vb  = (const float*)d_in[8];
    const float* gam = (const float*)d_in[9];
    const float* cow = (const float*)d_in[10];
    const float* gng = (const float*)d_in[11];
    const float* gnb = (const float*)d_in[12];
    float* out = (float*)d_out;

    void *p;
#define SYM(var, sym) cudaGetSymbolAddress(&p, sym); auto* var = (decltype(&sym[0]))p;
    SYM(xh, g_xh) SYM(xl, g_xl) SYM(zh, g_zh) SYM(zl, g_zl)
    SYM(z, g_z) SYM(z2, g_z2) SYM(qk, g_qk) SYM(v, g_v)
    SYM(attn, g_attn) SYM(acc, g_acc) SYM(cl, g_cl)
    SYM(c1h, g_c1h) SYM(c1l, g_c1l) SYM(qkh, g_qkh) SYM(qkl, g_qkl)
    SYM(vh, g_vh) SYM(vl, g_vl) SYM(w9h, g_w9h) SYM(w9l, g_w9l)
    SYM(bqk, g_bqk) SYM(st, g_stat)
#undef SYM

    const int SC_SM = 50688, AG_SM = 87552;
    cudaFuncSetAttribute(scores_kernel, cudaFuncAttributeMaxDynamicSharedMemorySize, SC_SM);
    cudaFuncSetAttribute(agg_h_kernel,  cudaFuncAttributeMaxDynamicSharedMemorySize, AG_SM);
    cudaFuncSetAttribute(agg_w_kernel,  cudaFuncAttributeMaxDynamicSharedMemorySize, AG_SM);
    cudaFuncSetAttribute(mma_gemm<0>, cudaFuncAttributeMaxDynamicSharedMemorySize, MG_SMEM);
    cudaFuncSetAttribute(mma_gemm<1>, cudaFuncAttributeMaxDynamicSharedMemorySize, MG_SMEM);
    cudaFuncSetAttribute(mma_gemm<2>, cudaFuncAttributeMaxDynamicSharedMemorySize, MG_SMEM);
    cudaFuncSetAttribute(mma_gemm<3>, cudaFuncAttributeMaxDynamicSharedMemorySize, MG_SMEM);

    split_x<<<dim3(288, 64, 2), 256>>>(x, xh, xl);
    split_w<<<(512 * 2048 + 255) / 256, 256>>>(c1w, c1h, c1l, 512 * 2048);
    split_qk<<<256, 256>>>(qw, kw, qkh, qkl);
    pack_bias<<<1, 128>>>(qb, kb, bqk);
    split_w<<<(512 * 512 + 255) / 256, 256>>>(vw, vh, vl, 512 * 512);
    split_w9<<<(9 * 512 * 512 + 255) / 256, 256>>>(cow, w9h, w9l);

    mma_gemm<0><<<dim3(72, 4, 2), 256, MG_SMEM>>>(xh, xl, c1h, c1l, c1b, z, zh, zl, 2048, 512);

    for (int it = 0; it < 2; it++) {
        float* zi = it ? z2 : z;
        float* zo = it ? z : z2;
        mma_gemm<1><<<dim3(72, 1, 2), 256, MG_SMEM>>>(zh, zl, qkh, qkl, bqk, qk, nullptr, nullptr, 512, 128);
        mma_gemm<2><<<dim3(72, 4, 2), 256, MG_SMEM>>>(zh, zl, vh, vl, vb, v, nullptr, nullptr, 512, 512);
        scores_kernel<<<dim3(96, 2, 2), 256, SC_SM>>>(qk, attn);
        softmax_kernel<<<2304, 256>>>(attn);
        agg_h_kernel<<<dim3(96, 4, 2), 256, AG_SM>>>(v, attn, acc);
        agg_w_kernel<<<dim3(96, 4, 2), 256, AG_SM>>>(v, attn, acc, zi, gam, zo, zh, zl);
    }

    mma_gemm<3><<<dim3(72, 4, 2), 256, MG_SMEM>>>(zh, zl, w9h, w9l, nullptr, cl, nullptr, nullptr, 512, 512);
    gn_stats_cl<<<64, 256>>>(cl, st);
    gn_out_kernel<<<dim3(288, 16, 2), 256>>>(cl, gng, gnb, st, out);
}

// round 10
// speedup vs baseline: 2.0165x; 1.0187x over previous
#include <cuda_runtime.h>
#include <cuda_bf16.h>
#include <cstdint>

#define HWSZ 9216
#define IMG  96
typedef __nv_bfloat16 bf16;

// ---------------- device scratch ----------------
__device__ bf16 g_xh[2 * HWSZ * 2048];
__device__ bf16 g_xl[2 * HWSZ * 2048];
__device__ bf16 g_zh[2 * HWSZ * 512];
__device__ bf16 g_zl[2 * HWSZ * 512];
__device__ float g_z   [2 * HWSZ * 512];
__device__ float g_z2  [2 * HWSZ * 512];
__device__ float g_qkv [2 * HWSZ * 640];   // [q 0:64 | k 64:128 | v 128:640]
__device__ float g_attn[2 * HWSZ * 192];
__device__ float g_acc [2 * HWSZ * 512];
__device__ float g_cl  [2 * HWSZ * 512];
__device__ bf16 g_c1h[512 * 2048], g_c1l[512 * 2048];
__device__ bf16 g_qvh[640 * 512],  g_qvl[640 * 512];
__device__ bf16 g_w9h[9 * 512 * 512], g_w9l[9 * 512 * 512];
__device__ float g_bqv[640];
__device__ float g_stat[128];

// ---------------- helpers ----------------
__device__ __forceinline__ uint32_t s2u(const void* p) {
    uint32_t a;
    asm("{ .reg .u64 t; cvta.to.shared.u64 t, %1; cvt.u32.u64 %0, t; }" : "=r"(a) : "l"(p));
    return a;
}
__device__ __forceinline__ void bsplit(float v, bf16* h, bf16* l) {
    bf16 hh = __float2bfloat16(v);
    *h = hh;
    *l = __float2bfloat16(v - __bfloat162float(hh));
}
__device__ __forceinline__ void mma16816(float* d, const uint32_t* a, const uint32_t* b) {
    asm volatile(
        "mma.sync.aligned.m16n8k16.row.col.f32.bf16.bf16.f32 "
        "{%0,%1,%2,%3}, {%4,%5,%6,%7}, {%8,%9}, {%0,%1,%2,%3};"
        : "+f"(d[0]), "+f"(d[1]), "+f"(d[2]), "+f"(d[3])
        : "r"(a[0]), "r"(a[1]), "r"(a[2]), "r"(a[3]), "r"(b[0]), "r"(b[1]));
}
__device__ __forceinline__ void cpasync16(uint32_t s, const void* g) {
    asm volatile("cp.async.cg.shared.global [%0], [%1], 16;" :: "r"(s), "l"(g));
}
__device__ __forceinline__ void ldm_x4(uint32_t* r, uint32_t addr) {
    asm volatile("ldmatrix.sync.aligned.m8n8.x4.shared.b16 {%0,%1,%2,%3}, [%4];"
                 : "=r"(r[0]), "=r"(r[1]), "=r"(r[2]), "=r"(r[3]) : "r"(addr));
}

// ---------------- packing / splitting ----------------
__global__ void split_x(const float* __restrict__ x, bf16* __restrict__ xh,
                        bf16* __restrict__ xl) {
    __shared__ float t[32][33];
    const int p0 = blockIdx.x * 32, c0 = blockIdx.y * 32, b = blockIdx.z;
    const int tx = threadIdx.x & 31, ty = threadIdx.x >> 5;
#pragma unroll
    for (int k = 0; k < 4; k++) {
        int cc = ty + k * 8;
        t[cc][tx] = x[((size_t)b * 2048 + c0 + cc) * HWSZ + p0 + tx];
    }
    __syncthreads();
#pragma unroll
    for (int k = 0; k < 4; k++) {
        int pl = ty + k * 8;
        float v = t[tx][pl];
        size_t o = ((size_t)b * HWSZ + p0 + pl) * 2048 + c0 + tx;
        bsplit(v, &xh[o], &xl[o]);
    }
}
__global__ void split_w(const float* __restrict__ w, bf16* __restrict__ wh,
                        bf16* __restrict__ wl, int n) {
    int i = blockIdx.x * 256 + threadIdx.x;
    if (i < n) bsplit(w[i], &wh[i], &wl[i]);
}
__global__ void split_qkv(const float* __restrict__ qw, const float* __restrict__ kw,
                          const float* __restrict__ vw, const float* __restrict__ qb,
                          const float* __restrict__ kb, const float* __restrict__ vb,
                          bf16* __restrict__ wh, bf16* __restrict__ wl,
                          float* __restrict__ bias) {
    int i = blockIdx.x * 256 + threadIdx.x;
    if (i < 640 * 512) {
        int m = i >> 9, k = i & 511;
        float v = (m < 64) ? qw[m * 512 + k]
                : (m < 128) ? kw[(m - 64) * 512 + k]
                            : vw[(m - 128) * 512 + k];
        bsplit(v, &wh[i], &wl[i]);
    }
    if (i < 640)
        bias[i] = (i < 64) ? qb[i] : (i < 128) ? kb[i - 64] : vb[i - 128];
}
__global__ void split_w9(const float* __restrict__ w, bf16* __restrict__ wh,
                         bf16* __restrict__ wl) {
    int d = blockIdx.x * 256 + threadIdx.x;
    if (d >= 9 * 512 * 512) return;
    int s = d / (512 * 512), r = d % (512 * 512);
    int o = r >> 9, ic = r & 511;
    bsplit(w[(o * 512 + ic) * 9 + s], &wh[d], &wl[d]);
}

// ---------------- bf16-split tensor-core GEMM (mma.sync + ldmatrix) -------
// D[128 pix][128 ch] = A[pix][K].B[ch][K]^T via Ah*Bh + Ah*Bl + Al*Bh
// MODE 0: conv1 (fp32 + bf16 hi/lo out), 2: qkv, 3: conv3 (9 shifts)
#define OPSZ 5120            // elems per operand tile (128*40)
#define OPB  10240           // bytes
#define BUFB 40960           // bytes per buffer (4 operands)
#define MG_SMEM (4864 + 2 * BUFB)
template <int MODE>
__global__ __launch_bounds__(256, 1)
void mma_gemm(const bf16* __restrict__ Ah, const bf16* __restrict__ Al,
              const bf16* __restrict__ Bh, const bf16* __restrict__ Bl,
              const float* __restrict__ bias, float* __restrict__ outf,
              bf16* __restrict__ oh, bf16* __restrict__ ol,
              int K, int Mtot)
{
    extern __shared__ char smem[];
    int* srcn = (int*)smem;
    bf16* tiles = (bf16*)(smem + 4864);
    const uint32_t smbase = s2u(tiles);
    const int tid = threadIdx.x, wid = tid >> 5, lane = tid & 31;
    const int n0 = blockIdx.x * 128, m0 = blockIdx.y * 128, b = blockIdx.z;

    if (MODE == 3 && tid < 128) {
        int n = n0 + tid, y = n / IMG, x = n - y * IMG;
#pragma unroll
        for (int s = 0; s < 9; s++) {
            int sy = y + s / 3 - 1, sx = x + s % 3 - 1;
            srcn[s * 128 + tid] = (sy >= 0 && sy < IMG && sx >= 0 && sx < IMG) ? sy * IMG + sx : -1;
        }
    }
    __syncthreads();

    const int g = tid >> 6, u = tid & 63, q = u & 3, rs = u >> 2;
    const bf16* srcp = (g == 0) ? Ah : (g == 1) ? Al : (g == 2) ? Bh : Bl;
    const int nch = (MODE == 3) ? 144 : (K >> 5);

    auto load_chunk = [&](int i) {
        bf16* t = tiles + (i & 1) * (BUFB / 2) + g * OPSZ;
        int s = 0, k0;
        if (MODE == 3) { s = i >> 4; k0 = (i & 15) << 5; } else { k0 = i << 5; }
#pragma unroll
        for (int j = 0; j < 8; j++) {
            int row = rs + j * 16;
            uint32_t sa = s2u(t + row * 40 + q * 8);
            if (g < 2) {
                long rn = -1;
                if (MODE == 3) { int sn = srcn[s * 128 + row]; if (sn >= 0) rn = sn; }
                else rn = n0 + row;
                if (rn >= 0)
                    cpasync16(sa, srcp + ((size_t)b * HWSZ + rn) * (size_t)K + k0 + q * 8);
                else
                    *(uint4*)(t + row * 40 + q * 8) = make_uint4(0, 0, 0, 0);
            } else {
                size_t mrow = (MODE == 3) ? ((size_t)s * 512 + m0 + row) : (size_t)(m0 + row);
                cpasync16(sa, srcp + mrow * (size_t)K + k0 + q * 8);
            }
        }
        asm volatile("cp.async.commit_group;" ::: "memory");
    };

    float acc[4][4][4];
#pragma unroll
    for (int mi = 0; mi < 4; mi++)
#pragma unroll
        for (int ni = 0; ni < 4; ni++)
#pragma unroll
            for (int r = 0; r < 4; r++) acc[mi][ni][r] = 0.f;

    const int wm = wid >> 2, wn = wid & 3;
    const int lr = lane >> 2, lc = (lane & 3) * 2;
    const int mq = lane >> 3, rowin = lane & 7;

    // precomputed ldmatrix byte offsets within an operand tile
    uint32_t aoff[2][4], boff[2][2];
#pragma unroll
    for (int ks = 0; ks < 2; ks++) {
#pragma unroll
        for (int mi = 0; mi < 4; mi++) {
            int row = wm * 64 + mi * 16 + (mq & 1) * 8 + rowin;
            int col = ks * 16 + (mq >> 1) * 8;
            aoff[ks][mi] = (uint32_t)(row * 40 + col) * 2;
        }
#pragma unroll
        for (int np = 0; np < 2; np++) {
            int n = wn * 32 + np * 16 + (mq >> 1) * 8 + rowin;
            int col = ks * 16 + (mq & 1) * 8;
            boff[ks][np] = (uint32_t)(n * 40 + col) * 2;
        }
    }

    load_chunk(0);
    asm volatile("cp.async.wait_group 0;" ::: "memory");
    __syncthreads();

    for (int i = 0; i < nch; i++) {
        if (i + 1 < nch) load_chunk(i + 1);
        const uint32_t tb = smbase + (i & 1) * BUFB;
        const uint32_t pAh = tb, pAl = tb + OPB, pBh = tb + 2 * OPB, pBl = tb + 3 * OPB;
#pragma unroll
        for (int ks = 0; ks < 2; ks++) {
            uint32_t ah[4][4], al[4][4], bh[4][2], bl[4][2], tmp[4];
#pragma unroll
            for (int mi = 0; mi < 4; mi++) {
                ldm_x4(ah[mi], pAh + aoff[ks][mi]);
                ldm_x4(al[mi], pAl + aoff[ks][mi]);
            }
#pragma unroll
            for (int np = 0; np < 2; np++) {
                ldm_x4(tmp, pBh + boff[ks][np]);
                bh[2*np][0] = tmp[0]; bh[2*np][1] = tmp[1];
                bh[2*np+1][0] = tmp[2]; bh[2*np+1][1] = tmp[3];
                ldm_x4(tmp, pBl + boff[ks][np]);
                bl[2*np][0] = tmp[0]; bl[2*np][1] = tmp[1];
                bl[2*np+1][0] = tmp[2]; bl[2*np+1][1] = tmp[3];
            }
#pragma unroll
            for (int mi = 0; mi < 4; mi++)
#pragma unroll
                for (int ni = 0; ni < 4; ni++) {
                    mma16816(acc[mi][ni], ah[mi], bh[ni]);
                    mma16816(acc[mi][ni], ah[mi], bl[ni]);
                    mma16816(acc[mi][ni], al[mi], bh[ni]);
                }
        }
        if (i + 1 < nch) asm volatile("cp.async.wait_group 0;" ::: "memory");
        __syncthreads();
    }

    // epilogue
#pragma unroll
    for (int mi = 0; mi < 4; mi++) {
#pragma unroll
        for (int ni = 0; ni < 4; ni++) {
            const int ch = m0 + wn * 32 + ni * 8 + lc;
            float b0 = 0.f, b1 = 0.f;
            if (MODE != 3) { b0 = __ldg(bias + ch); b1 = __ldg(bias + ch + 1); }
#pragma unroll
            for (int hh = 0; hh < 2; hh++) {
                const int pix = n0 + wm * 64 + mi * 16 + lr + hh * 8;
                const size_t prow = (size_t)b * HWSZ + pix;
                float v0 = acc[mi][ni][hh * 2] + b0;
                float v1 = acc[mi][ni][hh * 2 + 1] + b1;
                float2 vv; vv.x = v0; vv.y = v1;
                *(float2*)(outf + prow * (size_t)Mtot + ch) = vv;
                if (MODE == 0) {
                    size_t o = prow * 512 + ch;
                    bf16 h0, l0, h1, l1;
                    bsplit(v0, &h0, &l0);
                    bsplit(v1, &h1, &l1);
                    __nv_bfloat162 th, tl;
                    th.x = h0; th.y = h1; tl.x = l0; tl.y = l1;
                    *(__nv_bfloat162*)(oh + o) = th;
                    *(__nv_bfloat162*)(ol + o) = tl;
                }
            }
        }
    }
}

// ---------------- attention scores (reads q,k from fused qkv) -------------
__global__ __launch_bounds__(256)
void scores_kernel(const float* __restrict__ qkv, float* __restrict__ attn) {
    extern __shared__ float sm[];
    float* Qs = sm;
    float* Ks = sm + 96 * 64;
    const int fix = blockIdx.x, dir = blockIdx.y, b = blockIdx.z;
    const int tid = threadIdx.x;
    for (int idx = tid; idx < 96 * 32; idx += 256) {
        int p = idx >> 5, f = idx & 31;
        size_t row = (size_t)b * HWSZ + (dir == 0 ? p * IMG + fix : fix * IMG + p);
        float4 v = *(const float4*)&qkv[row * 640 + f * 4];
        if (f < 16) *(float4*)&Qs[p * 64 + f * 4] = v;
        else        *(float4*)&Ks[p * 68 + (f - 16) * 4] = v;
    }
    __syncthreads();
    for (int idx = tid; idx < 9216; idx += 256) {
        int p = idx / 96, r = idx - p * 96;
        const float* qp = &Qs[p * 64];
        const float* kp = &Ks[r * 68];
        float a0 = 0.f, a1 = 0.f, a2 = 0.f, a3 = 0.f;
#pragma unroll
        for (int t = 0; t < 16; t++) {
            float4 a = *(const float4*)&qp[t * 4];
            float4 k = *(const float4*)&kp[t * 4];
            a0 += a.x * k.x; a1 += a.y * k.y; a2 += a.z * k.z; a3 += a.w * k.w;
        }
        float val = (a0 + a1) + (a2 + a3);
        if (dir == 0 && r == p) val = -1e30f;
        size_t o = (dir == 0)
            ? ((size_t)b * HWSZ + p * IMG + fix) * 192 + r
            : ((size_t)b * HWSZ + fix * IMG + p) * 192 + 96 + r;
        attn[o] = val;
    }
}

__global__ __launch_bounds__(256)
void softmax_kernel(float* __restrict__ attn) {
    const int warp = threadIdx.x >> 5, lane = threadIdx.x & 31;
    const int pix = blockIdx.x * 8 + warp;
    float* p = attn + (size_t)pix * 192;
    float v[6];
#pragma unroll
    for (int t = 0; t < 6; t++) v[t] = p[lane + 32 * t];
    float m = v[0];
#pragma unroll
    for (int t = 1; t < 6; t++) m = fmaxf(m, v[t]);
#pragma unroll
    for (int off = 16; off > 0; off >>= 1) m = fmaxf(m, __shfl_xor_sync(0xffffffffu, m, off));
    float s = 0.f;
#pragma unroll
    for (int t = 0; t < 6; t++) { v[t] = __expf(v[t] - m); s += v[t]; }
#pragma unroll
    for (int off = 16; off > 0; off >>= 1) s += __shfl_xor_sync(0xffffffffu, s, off);
    float inv = 1.f / s;
#pragma unroll
    for (int t = 0; t < 6; t++) p[lane + 32 * t] = v[t] * inv;
}

// ---------------- aggregation along h (V = qkv + 128, stride 640) ---------
__global__ __launch_bounds__(256)
void agg_h_kernel(const float* __restrict__ V, const float* __restrict__ attn,
                  float* __restrict__ accb) {
    extern __shared__ float sm[];
    float* Vs = sm;
    float* At = sm + 96 * 128;
    const int w = blockIdx.x, c0 = blockIdx.y * 128, b = blockIdx.z;
    const int tid = threadIdx.x;
    for (int idx = tid; idx < 96 * 128; idx += 256) {
        int i = idx >> 7, cc = idx & 127;
        Vs[idx] = V[((size_t)b * HWSZ + i * IMG + w) * 640 + c0 + cc];
    }
    for (int idx = tid; idx < 9216; idx += 256) {
        int h = idx / 96, i = idx - h * 96;
        At[i * 100 + h] = attn[((size_t)b * HWSZ + h * IMG + w) * 192 + i];
    }
    __syncthreads();
    const int cc = tid & 127, h0 = (tid >> 7) * 48;
    float acc[48];
#pragma unroll
    for (int r = 0; r < 48; r++) acc[r] = 0.f;
    for (int i = 0; i < 96; i++) {
        float vv = Vs[i * 128 + cc];
        const float* ar = &At[i * 100 + h0];
#pragma unroll
        for (int r = 0; r < 12; r++) {
            float4 a = *(const float4*)&ar[r * 4];
            acc[4*r] += vv*a.x; acc[4*r+1] += vv*a.y; acc[4*r+2] += vv*a.z; acc[4*r+3] += vv*a.w;
        }
    }
#pragma unroll
    for (int h = 0; h < 48; h++)
        accb[((size_t)b * HWSZ + (h0 + h) * IMG + w) * 512 + c0 + cc] = acc[h];
}

// ---------------- aggregation along w + epilogue (emits bf16 hi/lo) ------
__global__ __launch_bounds__(256)
void agg_w_kernel(const float* __restrict__ V, const float* __restrict__ attn,
                  const float* __restrict__ accb, const float* __restrict__ zin,
                  const float* __restrict__ gamma, float* __restrict__ zout,
                  bf16* __restrict__ zh, bf16* __restrict__ zl) {
    extern __shared__ float sm[];
    float* Vs = sm;
    float* At = sm + 96 * 128;
    const int h = blockIdx.x, c0 = blockIdx.y * 128, b = blockIdx.z;
    const int tid = threadIdx.x;
    for (int idx = tid; idx < 96 * 128; idx += 256) {
        int j = idx >> 7, cc = idx & 127;
        Vs[idx] = V[((size_t)b * HWSZ + h * IMG + j) * 640 + c0 + cc];
    }
    for (int idx = tid; idx < 9216; idx += 256) {
        int w = idx / 96, j = idx - w * 96;
        At[j * 100 + w] = attn[((size_t)b * HWSZ + h * IMG + w) * 192 + 96 + j];
    }
    __syncthreads();
    const int cc = tid & 127, w0 = (tid >> 7) * 48;
    float acc[48];
#pragma unroll
    for (int r = 0; r < 48; r++) acc[r] = 0.f;
    for (int j = 0; j < 96; j++) {
        float vv = Vs[j * 128 + cc];
        const float* ar = &At[j * 100 + w0];
#pragma unroll
        for (int r = 0; r < 12; r++) {
            float4 a = *(const float4*)&ar[r * 4];
            acc[4*r] += vv*a.x; acc[4*r+1] += vv*a.y; acc[4*r+2] += vv*a.z; acc[4*r+3] += vv*a.w;
        }
    }
    const float g = gamma[0];
#pragma unroll
    for (int w = 0; w < 48; w++) {
        size_t o = ((size_t)b * HWSZ + h * IMG + w0 + w) * 512 + c0 + cc;
        float val = g * (acc[w] + accb[o]) + zin[o];
        zout[o] = val;
        bsplit(val, &zh[o], &zl[o]);
    }
}

// ---------------- GroupNorm ----------------
__global__ __launch_bounds__(256)
void gn_stats_cl(const float* __restrict__ x, float* __restrict__ stat) {
    const int b = blockIdx.x >> 5, gg = blockIdx.x & 31;
    const float* base = x + (size_t)b * HWSZ * 512 + gg * 16;
    float s = 0.f, ss = 0.f;
    for (int idx = threadIdx.x; idx < HWSZ * 4; idx += 256) {
        int pix = idx >> 2, q = idx & 3;
        float4 v = *(const float4*)(base + (size_t)pix * 512 + q * 4);
        s  += (v.x + v.y) + (v.z + v.w);
        ss += (v.x*v.x + v.y*v.y) + (v.z*v.z + v.w*v.w);
    }
    __shared__ float rs[8], rss[8];
    const int lane = threadIdx.x & 31, warp = threadIdx.x >> 5;
#pragma unroll
    for (int off = 16; off > 0; off >>= 1) {
        s  += __shfl_xor_sync(0xffffffffu, s, off);
        ss += __shfl_xor_sync(0xffffffffu, ss, off);
    }
    if (lane == 0) { rs[warp] = s; rss[warp] = ss; }
    __syncthreads();
    if (threadIdx.x == 0) {
        float S = 0.f, SS = 0.f;
#pragma unroll
        for (int i = 0; i < 8; i++) { S += rs[i]; SS += rss[i]; }
        float mean = S / 147456.f;
        float var = SS / 147456.f - mean * mean;
        stat[2 * blockIdx.x] = mean;
        stat[2 * blockIdx.x + 1] = rsqrtf(var + 1e-5f);
    }
}

__global__ __launch_bounds__(256)
void gn_out_kernel(const float* __restrict__ cl, const float* __restrict__ gam,
                   const float* __restrict__ bet, const float* __restrict__ stat,
                   float* __restrict__ out) {
    __shared__ float t[32][33];
    const int p0 = blockIdx.x * 32, c0 = blockIdx.y * 32, b = blockIdx.z;
    const int tx = threadIdx.x & 31, ty = threadIdx.x >> 5;
#pragma unroll
    for (int k = 0; k < 4; k++) {
        int pl = ty + k * 8;
        t[pl][tx] = cl[((size_t)b * HWSZ + p0 + pl) * 512 + c0 + tx];
    }
    __syncthreads();
#pragma unroll
    for (int k = 0; k < 4; k++) {
        int c = c0 + ty + k * 8;
        int sg = b * 32 + (c >> 4);
        float sc = stat[2 * sg + 1] * gam[c];
        float sh = bet[c] - stat[2 * sg] * sc;
        out[((size_t)b * 512 + c) * HWSZ + p0 + tx] = t[tx][ty + k * 8] * sc + sh;
    }
}

// ---------------- launch ----------------
extern "C" void kernel_launch(void* const* d_in, const int* in_sizes, int n_in,
                              void* d_out, int out_size) {
    const float* x   = (const float*)d_in[0];
    const float* c1w = (const float*)d_in[1];
    const float* c1b = (const float*)d_in[2];
    const float* qw  = (const float*)d_in[3];
    const float* qb  = (const float*)d_in[4];
    const float* kw  = (const float*)d_in[5];
    const float* kb  = (const float*)d_in[6];
    const float* vw  = (const float*)d_in[7];
    const float* vb  = (const float*)d_in[8];
    const float* gam = (const float*)d_in[9];
    const float* cow = (const float*)d_in[10];
    const float* gng = (const float*)d_in[11];
    const float* gnb = (const float*)d_in[12];
    float* out = (float*)d_out;

    void *p;
#define SYM(var, sym) cudaGetSymbolAddress(&p, sym); auto* var = (decltype(&sym[0]))p;
    SYM(xh, g_xh) SYM(xl, g_xl) SYM(zh, g_zh) SYM(zl, g_zl)
    SYM(z, g_z) SYM(z2, g_z2) SYM(qkv, g_qkv)
    SYM(attn, g_attn) SYM(acc, g_acc) SYM(cl, g_cl)
    SYM(c1h, g_c1h) SYM(c1l, g_c1l) SYM(qvh, g_qvh) SYM(qvl, g_qvl)
    SYM(w9h, g_w9h) SYM(w9l, g_w9l)
    SYM(bqv, g_bqv) SYM(st, g_stat)
#undef SYM

    const int SC_SM = 50688, AG_SM = 87552;
    cudaFuncSetAttribute(scores_kernel, cudaFuncAttributeMaxDynamicSharedMemorySize, SC_SM);
    cudaFuncSetAttribute(agg_h_kernel,  cudaFuncAttributeMaxDynamicSharedMemorySize, AG_SM);
    cudaFuncSetAttribute(agg_w_kernel,  cudaFuncAttributeMaxDynamicSharedMemorySize, AG_SM);
    cudaFuncSetAttribute(mma_gemm<0>, cudaFuncAttributeMaxDynamicSharedMemorySize, MG_SMEM);
    cudaFuncSetAttribute(mma_gemm<2>, cudaFuncAttributeMaxDynamicSharedMemorySize, MG_SMEM);
    cudaFuncSetAttribute(mma_gemm<3>, cudaFuncAttributeMaxDynamicSharedMemorySize, MG_SMEM);

    split_x<<<dim3(288, 64, 2), 256>>>(x, xh, xl);
    split_w<<<(512 * 2048 + 255) / 256, 256>>>(c1w, c1h, c1l, 512 * 2048);
    split_qkv<<<(640 * 512 + 255) / 256, 256>>>(qw, kw, vw, qb, kb, vb, qvh, qvl, bqv);
    split_w9<<<(9 * 512 * 512 + 255) / 256, 256>>>(cow, w9h, w9l);

    mma_gemm<0><<<dim3(72, 4, 2), 256, MG_SMEM>>>(xh, xl, c1h, c1l, c1b, z, zh, zl, 2048, 512);

    for (int it = 0; it < 2; it++) {
        float* zi = it ? z2 : z;
        float* zo = it ? z : z2;
        mma_gemm<2><<<dim3(72, 5, 2), 256, MG_SMEM>>>(zh, zl, qvh, qvl, bqv, qkv, nullptr, nullptr, 512, 640);
        scores_kernel<<<dim3(96, 2, 2), 256, SC_SM>>>(qkv, attn);
        softmax_kernel<<<2304, 256>>>(attn);
        agg_h_kernel<<<dim3(96, 4, 2), 256, AG_SM>>>(qkv + 128, attn, acc);
        agg_w_kernel<<<dim3(96, 4, 2), 256, AG_SM>>>(qkv + 128, attn, acc, zi, gam, zo, zh, zl);
    }

    mma_gemm<3><<<dim3(72, 4, 2), 256, MG_SMEM>>>(zh, zl, w9h, w9l, nullptr, cl, nullptr, nullptr, 512, 512);
    gn_stats_cl<<<64, 256>>>(cl, st);
    gn_out_kernel<<<dim3(288, 16, 2), 256>>>(cl, gng, gnb, st, out);
}